// round 10
// baseline (speedup 1.0000x reference)
#include <cuda_runtime.h>

#define NUM_USERS 50000
#define NUM_ITEMS 50000
#define D 64
#define DV 16
#define N_NODES (NUM_USERS + NUM_ITEMS)
#define N_EDGES 500000
#define NNZ_G 1000000
#define NNZ_GX 2000000
#define BATCH 8192

// ---- static device scratch (zero-init at load; maintained zero across replays) ----
__device__ float g_A[(size_t)N_NODES * D];
__device__ float g_B[(size_t)N_NODES * D];     // zeroed by k_combine each layer
__device__ float g_U[(size_t)N_NODES * D];     // ditto
__device__ float g_acc[(size_t)N_NODES * D];   // zeroed by k_init each call
__device__ float g_deg[N_NODES];               // counted in k_scatter, zeroed in k_dot

// CSR of gx nnz grouped by SOURCE edge (gx_cols; 500k bins, avg 4 entries)
__device__ int  g_ecnt[N_EDGES];               // re-zeroed by k_scan
__device__ int  g_eoff[N_EDGES + 1];
__device__ int  g_ecur[N_EDGES];
__device__ int2 g_es[NNZ_GX];                  // {tu[r] | ti[r]<<16, val bits}

// fire-and-forget vector reduction (RED.E.ADD.F32x4), sm_90+
__device__ __forceinline__ void red_add_f32x4(float4* addr, float4 v) {
    asm volatile("red.global.add.v4.f32 [%0], {%1, %2, %3, %4};"
                 :: "l"(addr), "f"(v.x), "f"(v.y), "f"(v.z), "f"(v.w)
                 : "memory");
}

// 1: count gx nnz per SOURCE edge (precondition ecnt=0: static init / k_scan cleanup)
__global__ void k_count(const int* __restrict__ gxc) {
    int t = blockIdx.x * blockDim.x + threadIdx.x;
    if (t >= NNZ_GX) return;
    atomicAdd(&g_ecnt[gxc[t]], 1);
}

// 2: single-block exclusive scan of 500k bins; zero ecnt behind itself
__global__ void k_scan() {
    __shared__ int ssum[1024];
    int tid = threadIdx.x;
    const int n = N_EDGES;
    int chunk = (n + 1023) / 1024;
    int beg = tid * chunk;
    int end = beg + chunk; if (end > n) end = n; if (beg > n) beg = n;
    int s = 0;
    for (int i = beg; i < end; ++i) s += g_ecnt[i];
    ssum[tid] = s;
    __syncthreads();
    for (int o = 1; o < 1024; o <<= 1) {
        int v = (tid >= o) ? ssum[tid - o] : 0;
        __syncthreads();
        ssum[tid] += v;
        __syncthreads();
    }
    int run = (tid == 0) ? 0 : ssum[tid - 1];
    for (int i = beg; i < end; ++i) {
        int c = g_ecnt[i];
        g_eoff[i] = run;
        g_ecur[i] = run;
        g_ecnt[i] = 0;          // cleanup for next replay
        run += c;
    }
    if (tid == 1023) g_eoff[n] = ssum[1023];
}

// 3: scatter gx entries (destination node pair + value) into source-sorted
//    array; also count node degrees (precondition deg=0: k_dot cleanup)
__global__ void k_scatter(const int* __restrict__ gxr, const int* __restrict__ gxc,
                          const float* __restrict__ gxv,
                          const int* __restrict__ tu, const int* __restrict__ ti) {
    int t = blockIdx.x * blockDim.x + threadIdx.x;
    if (t < NNZ_GX) {
        int r = gxr[t];
        unsigned du = (unsigned)tu[r];
        unsigned dir = (unsigned)ti[r];
        int p = atomicAdd(&g_ecur[gxc[t]], 1);
        g_es[p] = make_int2((int)(du | (dir << 16)), __float_as_int(gxv[t]));
    }
    if (t < N_EDGES) {
        atomicAdd(&g_deg[tu[t]], 1.f);
        atomicAdd(&g_deg[NUM_USERS + ti[t]], 1.f);
    }
}

// 4: init embeddings + acc (B,U maintained zero by combine)
__global__ void k_init(const float* __restrict__ ue, const float* __restrict__ ie) {
    int t = blockIdx.x * blockDim.x + threadIdx.x;
    if (t >= N_NODES * DV) return;
    float4 v;
    if (t < NUM_USERS * DV) v = ((const float4*)ue)[t];
    else                    v = ((const float4*)ie)[t - NUM_USERS * DV];
    ((float4*)g_A)[t]   = v;
    ((float4*)g_acc)[t] = make_float4(0.f, 0.f, 0.f, 0.f);
}

// push spmm (R4-proven): B[r] += v * A[c], 2 nnz per thread
__global__ void __launch_bounds__(256) k_spmm_g(const int* __restrict__ rows,
                                                const int* __restrict__ cols,
                                                const float* __restrict__ vals) {
    int t = blockIdx.x * blockDim.x + threadIdx.x;   // < NNZ_G/2 * 16 = 8M
    int p = t >> 4;
    int j = t & 15;
    if (p >= NNZ_G / 2) return;
    int2   r2 = ((const int2*)rows)[p];
    int2   c2 = ((const int2*)cols)[p];
    float2 v2 = ((const float2*)vals)[p];
    const float4* Av = (const float4*)g_A;
    float4 x0 = Av[c2.x * DV + j];
    float4 x1 = Av[c2.y * DV + j];
    float4 y0 = make_float4(v2.x * x0.x, v2.x * x0.y, v2.x * x0.z, v2.x * x0.w);
    float4 y1 = make_float4(v2.y * x1.x, v2.y * x1.y, v2.y * x1.z, v2.y * x1.w);
    red_add_f32x4(((float4*)g_B) + r2.x * DV + j, y0);
    red_add_f32x4(((float4*)g_B) + r2.y * DV + j, y1);
}

// source-deduped gx push: per (source edge e, chunk j):
//   gather x0 = B[tu[e]] (+cat_low), x1 = B[50000+ti[e]] (+cat_high) ONCE,
//   then for each nnz in seg(e): RED(U[du], v*x0); RED(U[di], v*x1).
// Loop body has NO dependent gathers — REDs are fire-and-forget.
template <int LAYER0>
__global__ void __launch_bounds__(256) k_gx_src(const int* __restrict__ tu,
                                                const int* __restrict__ ti,
                                                const int* __restrict__ i2c,
                                                const float* __restrict__ cat) {
    int t = blockIdx.x * blockDim.x + threadIdx.x;   // < N_EDGES * 16 = 8M
    int e = t >> 4;
    int j = t & 15;
    if (e >= N_EDGES) return;
    int i = g_eoff[e], end = g_eoff[e + 1];
    if (i == end) return;
    int su = tu[e];                 // coalesced (broadcast within edge's 16 threads)
    int tie = ti[e];
    const float4* Bv = (const float4*)g_B;
    float4 x0 = Bv[su * DV + j];
    float4 x1 = Bv[(NUM_USERS + tie) * DV + j];
    if (LAYER0) {
        int cidx = i2c[tie];
        const float4* catv = (const float4*)cat + cidx * 32;
        float4 c0 = catv[j];
        float4 c1 = catv[16 + j];
        x0.x += c0.x; x0.y += c0.y; x0.z += c0.z; x0.w += c0.w;
        x1.x += c1.x; x1.y += c1.y; x1.z += c1.z; x1.w += c1.w;
    }
    float4* Uv = (float4*)g_U;
    for (; i < end; ++i) {
        int2 E = g_es[i];
        float v = __int_as_float(E.y);
        unsigned d = (unsigned)E.x;
        int du = (int)(d & 0xFFFFu);
        int di = NUM_USERS + (int)(d >> 16);
        float4 y0 = make_float4(v * x0.x, v * x0.y, v * x0.z, v * x0.w);
        float4 y1 = make_float4(v * x1.x, v * x1.y, v * x1.z, v * x1.w);
        red_add_f32x4(Uv + du * DV + j, y0);
        red_add_f32x4(Uv + di * DV + j, y1);
    }
}

// A = 0.5 * (U/(deg+1e-9) + B);  acc += A;  zero B,U for next layer/replay
__global__ void k_combine() {
    int t0 = (blockIdx.x * blockDim.x + threadIdx.x) * 2;
    if (t0 >= N_NODES * DV) return;
    float4 z = make_float4(0.f, 0.f, 0.f, 0.f);
    #pragma unroll
    for (int q = 0; q < 2; ++q) {
        int t = t0 + q;
        int n = t >> 4;
        float inv = 0.5f / (g_deg[n] + 1e-9f);
        float4 u = ((const float4*)g_U)[t];
        float4 b = ((const float4*)g_B)[t];
        float4 a;
        a.x = u.x * inv + 0.5f * b.x;
        a.y = u.y * inv + 0.5f * b.y;
        a.z = u.z * inv + 0.5f * b.z;
        a.w = u.w * inv + 0.5f * b.w;
        ((float4*)g_A)[t] = a;
        float4 ac = ((float4*)g_acc)[t];
        ac.x += a.x; ac.y += a.y; ac.z += a.z; ac.w += a.w;
        ((float4*)g_acc)[t] = ac;
        ((float4*)g_B)[t] = z;
        ((float4*)g_U)[t] = z;
    }
}

// gamma[b] = dot(acc[u], acc[50000+i]) / 9; also zero deg for next replay
__global__ void k_dot(const int* __restrict__ users, const int* __restrict__ items,
                      float* __restrict__ out) {
    int t = blockIdx.x * blockDim.x + threadIdx.x;
    if (t < N_NODES) g_deg[t] = 0.f;
    int b = t >> 5;
    if (b >= BATCH) return;
    int lane = t & 31;
    const float2* au = (const float2*)(g_acc + (size_t)users[b] * D);
    const float2* ai = (const float2*)(g_acc + (size_t)(NUM_USERS + items[b]) * D);
    float2 x = au[lane], y = ai[lane];
    float s = x.x * y.x + x.y * y.y;
    #pragma unroll
    for (int o = 16; o; o >>= 1) s += __shfl_down_sync(0xffffffffu, s, o);
    if (lane == 0) out[b] = s * (1.f / 9.f);
}

extern "C" void kernel_launch(void* const* d_in, const int* in_sizes, int n_in,
                              void* d_out, int out_size) {
    const float* user_emb = (const float*)d_in[0];
    const float* item_emb = (const float*)d_in[1];
    const float* cat_emb  = (const float*)d_in[2];
    const float* g_vals   = (const float*)d_in[3];
    const float* gx_vals  = (const float*)d_in[4];
    const int*   g_rows   = (const int*)d_in[5];
    const int*   g_cols   = (const int*)d_in[6];
    const int*   gx_rows  = (const int*)d_in[7];
    const int*   gx_cols  = (const int*)d_in[8];
    const int*   tu       = (const int*)d_in[9];
    const int*   ti       = (const int*)d_in[10];
    const int*   i2c      = (const int*)d_in[11];
    const int*   users    = (const int*)d_in[12];
    const int*   items    = (const int*)d_in[13];
    float* out = (float*)d_out;

    const int TB = 256;
    int node_grid = (N_NODES * DV + TB - 1) / TB;        // 6250
    int comb_grid = (N_NODES * DV / 2 + TB - 1) / TB;    // 3125
    int nnz_grid  = (NNZ_GX + TB - 1) / TB;              // 7813
    int g_grid    = (NNZ_G / 2 * 16) / TB;               // 31250
    int gx_grid   = (N_EDGES * 16) / TB;                 // 31250
    int dot_grid  = (BATCH * 32 + TB - 1) / TB;          // 1024

    k_count<<<nnz_grid, TB>>>(gx_cols);                              // 1
    k_scan<<<1, 1024>>>();                                           // 2
    k_scatter<<<nnz_grid, TB>>>(gx_rows, gx_cols, gx_vals, tu, ti);  // 3
    k_init<<<node_grid, TB>>>(user_emb, item_emb);                   // 4
    for (int L = 0; L < 3; ++L) {
        k_spmm_g<<<g_grid, TB>>>(g_rows, g_cols, g_vals);            // 5, 8, 11
        if (L == 0) k_gx_src<1><<<gx_grid, TB>>>(tu, ti, i2c, cat_emb); // 6 <- ncu often lands near here
        else        k_gx_src<0><<<gx_grid, TB>>>(tu, ti, i2c, cat_emb);
        k_combine<<<comb_grid, TB>>>();                              // 7, 10, 13
    }
    k_dot<<<dot_grid, TB>>>(users, items, out);                      // 14
}

// round 11
// speedup vs baseline: 1.0658x; 1.0658x over previous
#include <cuda_runtime.h>

#define NUM_USERS 50000
#define NUM_ITEMS 50000
#define D 64
#define DV 16
#define N_NODES (NUM_USERS + NUM_ITEMS)
#define N_EDGES 500000
#define NNZ_G 1000000
#define NNZ_GX 2000000
#define BATCH 8192

// ---- static device scratch (zero-init at load; replay-safe state machine) ----
__device__ float g_A[(size_t)N_NODES * D];
__device__ float g_B[(size_t)N_NODES * D];     // zeroed by k_combine each layer
__device__ float g_U[(size_t)N_NODES * D];     // ditto
__device__ float g_acc[(size_t)N_NODES * D];   // zeroed by k_init_count each call
__device__ float g_deg[N_NODES];               // counted here, zeroed by k_dot

// gx nnz sorted by SOURCE edge (gx_cols): flat 16B entries, R4-shaped consumption
__device__ int  g_ecnt[N_EDGES];               // re-zeroed by k_scan
__device__ int  g_ecur[N_EDGES];
__device__ int4 g_es4[NNZ_GX];                 // {tu[c]|ti[c]<<16, tu[r]|ti[r]<<16, vbits, cidx}

// g nnz sorted by COLUMN: flat 16B entries
__device__ int  g_gcnt[N_NODES];               // re-zeroed by k_scan
__device__ int  g_gcur[N_NODES];
__device__ int4 g_gs4[NNZ_G];                  // {col, row, vbits, 0}

// fire-and-forget vector reduction (RED.E.ADD.F32x4), sm_90+
__device__ __forceinline__ void red_add_f32x4(float4* addr, float4 v) {
    asm volatile("red.global.add.v4.f32 [%0], {%1, %2, %3, %4};"
                 :: "l"(addr), "f"(v.x), "f"(v.y), "f"(v.z), "f"(v.w)
                 : "memory");
}

// 1: init A/acc + count gx-by-source, g-by-col, node degrees (all outputs disjoint)
__global__ void k_init_count(const float* __restrict__ ue, const float* __restrict__ ie,
                             const int* __restrict__ gxc, const int* __restrict__ gcols,
                             const int* __restrict__ tu, const int* __restrict__ ti) {
    int t = blockIdx.x * blockDim.x + threadIdx.x;
    if (t < N_NODES * DV) {
        float4 v;
        if (t < NUM_USERS * DV) v = ((const float4*)ue)[t];
        else                    v = ((const float4*)ie)[t - NUM_USERS * DV];
        ((float4*)g_A)[t]   = v;
        ((float4*)g_acc)[t] = make_float4(0.f, 0.f, 0.f, 0.f);
    }
    if (t < NNZ_GX) atomicAdd(&g_ecnt[gxc[t]], 1);
    if (t < NNZ_G)  atomicAdd(&g_gcnt[gcols[t]], 1);
    if (t < N_EDGES) {
        atomicAdd(&g_deg[tu[t]], 1.f);
        atomicAdd(&g_deg[NUM_USERS + ti[t]], 1.f);
    }
}

// 2: exclusive scans (500k gx bins, then 100k g bins); zero counts behind
__device__ void scan_one(int* cnt, int* cur, int n, int* ssum) {
    int tid = threadIdx.x;
    int chunk = (n + 1023) / 1024;
    int beg = tid * chunk;
    int end = beg + chunk; if (end > n) end = n; if (beg > n) beg = n;
    int s = 0;
    for (int i = beg; i < end; ++i) s += cnt[i];
    ssum[tid] = s;
    __syncthreads();
    for (int o = 1; o < 1024; o <<= 1) {
        int v = (tid >= o) ? ssum[tid - o] : 0;
        __syncthreads();
        ssum[tid] += v;
        __syncthreads();
    }
    int run = (tid == 0) ? 0 : ssum[tid - 1];
    for (int i = beg; i < end; ++i) {
        int c = cnt[i];
        cur[i] = run;
        cnt[i] = 0;             // cleanup for next replay
        run += c;
    }
    __syncthreads();
}
__global__ void k_scan() {
    __shared__ int ssum[1024];
    scan_one(g_ecnt, g_ecur, N_EDGES, ssum);
    scan_one(g_gcnt, g_gcur, N_NODES, ssum);
}

// 3: scatter both nnz streams into sorted flat-entry arrays
__global__ void k_scatter(const int* __restrict__ gxr, const int* __restrict__ gxc,
                          const float* __restrict__ gxv,
                          const int* __restrict__ grows, const int* __restrict__ gcols,
                          const float* __restrict__ gvals,
                          const int* __restrict__ tu, const int* __restrict__ ti,
                          const int* __restrict__ i2c) {
    int t = blockIdx.x * blockDim.x + threadIdx.x;
    if (t < NNZ_GX) {
        int c = gxc[t];
        int r = gxr[t];
        unsigned suc = (unsigned)tu[c];
        unsigned sic = (unsigned)ti[c];
        unsigned dur = (unsigned)tu[r];
        unsigned dir = (unsigned)ti[r];
        int cidx = i2c[(int)sic];
        int p = atomicAdd(&g_ecur[c], 1);
        g_es4[p] = make_int4((int)(suc | (sic << 16)),
                             (int)(dur | (dir << 16)),
                             __float_as_int(gxv[t]), cidx);
    }
    if (t < NNZ_G) {
        int p = atomicAdd(&g_gcur[gcols[t]], 1);
        g_gs4[p] = make_int4(gcols[t], grows[t], __float_as_int(gvals[t]), 0);
    }
}

// 4: push spmm over column-sorted entries (R4 shape, 2 nnz/thread)
__global__ void __launch_bounds__(256) k_spmm_g() {
    int t = blockIdx.x * blockDim.x + threadIdx.x;   // < NNZ_G/2 * 16 = 8M
    int p = t >> 4;
    int j = t & 15;
    if (p >= NNZ_G / 2) return;
    int4 Ea = g_gs4[2 * p];
    int4 Eb = g_gs4[2 * p + 1];
    const float4* Av = (const float4*)g_A;
    float4 x0 = Av[Ea.x * DV + j];
    float4 x1 = Av[Eb.x * DV + j];
    float va = __int_as_float(Ea.z);
    float vb = __int_as_float(Eb.z);
    float4 y0 = make_float4(va * x0.x, va * x0.y, va * x0.z, va * x0.w);
    float4 y1 = make_float4(vb * x1.x, vb * x1.y, vb * x1.z, vb * x1.w);
    red_add_f32x4(((float4*)g_B) + Ea.y * DV + j, y0);
    red_add_f32x4(((float4*)g_B) + Eb.y * DV + j, y1);
}

// 5: gx push over source-sorted entries (R4 shape, 2 nnz/thread, 4 gathers/4 REDs)
template <int LAYER0>
__global__ void __launch_bounds__(256) k_gx(const float* __restrict__ cat) {
    int t = blockIdx.x * blockDim.x + threadIdx.x;   // < NNZ_GX/2 * 16 = 16M
    int p = t >> 4;
    int j = t & 15;
    if (p >= NNZ_GX / 2) return;
    int4 Ea = g_es4[2 * p];
    int4 Eb = g_es4[2 * p + 1];
    const float4* Bv = (const float4*)g_B;
    unsigned sa = (unsigned)Ea.x, sb = (unsigned)Eb.x;
    int sua = (int)(sa & 0xFFFFu), sia = NUM_USERS + (int)(sa >> 16);
    int sub = (int)(sb & 0xFFFFu), sib = NUM_USERS + (int)(sb >> 16);
    float4 xa0 = Bv[sua * DV + j];
    float4 xa1 = Bv[sia * DV + j];
    float4 xb0 = Bv[sub * DV + j];
    float4 xb1 = Bv[sib * DV + j];
    if (LAYER0) {
        const float4* catv = (const float4*)cat;
        float4 ca0 = catv[Ea.w * 32 + j];
        float4 ca1 = catv[Ea.w * 32 + 16 + j];
        float4 cb0 = catv[Eb.w * 32 + j];
        float4 cb1 = catv[Eb.w * 32 + 16 + j];
        xa0.x += ca0.x; xa0.y += ca0.y; xa0.z += ca0.z; xa0.w += ca0.w;
        xa1.x += ca1.x; xa1.y += ca1.y; xa1.z += ca1.z; xa1.w += ca1.w;
        xb0.x += cb0.x; xb0.y += cb0.y; xb0.z += cb0.z; xb0.w += cb0.w;
        xb1.x += cb1.x; xb1.y += cb1.y; xb1.z += cb1.z; xb1.w += cb1.w;
    }
    float va = __int_as_float(Ea.z);
    float vb = __int_as_float(Eb.z);
    unsigned da = (unsigned)Ea.y, db = (unsigned)Eb.y;
    int dua = (int)(da & 0xFFFFu), dia = NUM_USERS + (int)(da >> 16);
    int dub = (int)(db & 0xFFFFu), dib = NUM_USERS + (int)(db >> 16);
    float4 ya0 = make_float4(va * xa0.x, va * xa0.y, va * xa0.z, va * xa0.w);
    float4 ya1 = make_float4(va * xa1.x, va * xa1.y, va * xa1.z, va * xa1.w);
    float4 yb0 = make_float4(vb * xb0.x, vb * xb0.y, vb * xb0.z, vb * xb0.w);
    float4 yb1 = make_float4(vb * xb1.x, vb * xb1.y, vb * xb1.z, vb * xb1.w);
    float4* Uv = (float4*)g_U;
    red_add_f32x4(Uv + dua * DV + j, ya0);
    red_add_f32x4(Uv + dia * DV + j, ya1);
    red_add_f32x4(Uv + dub * DV + j, yb0);
    red_add_f32x4(Uv + dib * DV + j, yb1);
}

// A = 0.5 * (U/(deg+1e-9) + B);  acc += A;  zero B,U for next layer/replay
__global__ void k_combine() {
    int t0 = (blockIdx.x * blockDim.x + threadIdx.x) * 2;
    if (t0 >= N_NODES * DV) return;
    float4 z = make_float4(0.f, 0.f, 0.f, 0.f);
    #pragma unroll
    for (int q = 0; q < 2; ++q) {
        int t = t0 + q;
        int n = t >> 4;
        float inv = 0.5f / (g_deg[n] + 1e-9f);
        float4 u = ((const float4*)g_U)[t];
        float4 b = ((const float4*)g_B)[t];
        float4 a;
        a.x = u.x * inv + 0.5f * b.x;
        a.y = u.y * inv + 0.5f * b.y;
        a.z = u.z * inv + 0.5f * b.z;
        a.w = u.w * inv + 0.5f * b.w;
        ((float4*)g_A)[t] = a;
        float4 ac = ((float4*)g_acc)[t];
        ac.x += a.x; ac.y += a.y; ac.z += a.z; ac.w += a.w;
        ((float4*)g_acc)[t] = ac;
        ((float4*)g_B)[t] = z;
        ((float4*)g_U)[t] = z;
    }
}

// gamma[b] = dot(acc[u], acc[50000+i]) / 9; zero deg for next replay
__global__ void k_dot(const int* __restrict__ users, const int* __restrict__ items,
                      float* __restrict__ out) {
    int t = blockIdx.x * blockDim.x + threadIdx.x;
    if (t < N_NODES) g_deg[t] = 0.f;
    int b = t >> 5;
    if (b >= BATCH) return;
    int lane = t & 31;
    const float2* au = (const float2*)(g_acc + (size_t)users[b] * D);
    const float2* ai = (const float2*)(g_acc + (size_t)(NUM_USERS + items[b]) * D);
    float2 x = au[lane], y = ai[lane];
    float s = x.x * y.x + x.y * y.y;
    #pragma unroll
    for (int o = 16; o; o >>= 1) s += __shfl_down_sync(0xffffffffu, s, o);
    if (lane == 0) out[b] = s * (1.f / 9.f);
}

extern "C" void kernel_launch(void* const* d_in, const int* in_sizes, int n_in,
                              void* d_out, int out_size) {
    const float* user_emb = (const float*)d_in[0];
    const float* item_emb = (const float*)d_in[1];
    const float* cat_emb  = (const float*)d_in[2];
    const float* g_vals   = (const float*)d_in[3];
    const float* gx_vals  = (const float*)d_in[4];
    const int*   g_rows   = (const int*)d_in[5];
    const int*   g_cols   = (const int*)d_in[6];
    const int*   gx_rows  = (const int*)d_in[7];
    const int*   gx_cols  = (const int*)d_in[8];
    const int*   tu       = (const int*)d_in[9];
    const int*   ti       = (const int*)d_in[10];
    const int*   i2c      = (const int*)d_in[11];
    const int*   users    = (const int*)d_in[12];
    const int*   items    = (const int*)d_in[13];
    float* out = (float*)d_out;

    const int TB = 256;
    int big_grid  = (NNZ_GX + TB - 1) / TB;              // 7813 (covers all prep ranges)
    int comb_grid = (N_NODES * DV / 2 + TB - 1) / TB;    // 3125
    int g_grid    = (NNZ_G / 2 * 16) / TB;               // 31250
    int gx_grid   = (NNZ_GX / 2 * 16) / TB;              // 62500
    int dot_grid  = (BATCH * 32 + TB - 1) / TB;          // 1024

    k_init_count<<<big_grid, TB>>>(user_emb, item_emb, gx_cols, g_cols, tu, ti); // 1
    k_scan<<<1, 1024>>>();                                                       // 2
    k_scatter<<<big_grid, TB>>>(gx_rows, gx_cols, gx_vals,
                                g_rows, g_cols, g_vals, tu, ti, i2c);            // 3
    for (int L = 0; L < 3; ++L) {
        k_spmm_g<<<g_grid, TB>>>();                                              // 4 <- profiled
        if (L == 0) k_gx<1><<<gx_grid, TB>>>(cat_emb);                           // 5
        else        k_gx<0><<<gx_grid, TB>>>(cat_emb);
        k_combine<<<comb_grid, TB>>>();
    }
    k_dot<<<dot_grid, TB>>>(users, items, out);
}

// round 12
// speedup vs baseline: 2.5568x; 2.3989x over previous
#include <cuda_runtime.h>

#define NUM_USERS 50000
#define NUM_ITEMS 50000
#define D 64
#define DV 16
#define N_NODES (NUM_USERS + NUM_ITEMS)
#define N_EDGES 500000
#define NNZ_G 1000000
#define NNZ_GX 2000000
#define BATCH 8192

#define BINS_PER_BLOCK 2048                 // 256 threads x 8 bins
#define GX_BLOCKS 245                       // ceil(500000/2048)
#define G_BLOCKS  49                        // ceil(100000/2048)

// ---- static device scratch (zero-init at load; replay-safe state machine) ----
__device__ float g_A[(size_t)N_NODES * D];
__device__ float g_B[(size_t)N_NODES * D];     // zeroed by k_combine each layer
__device__ float g_U[(size_t)N_NODES * D];     // ditto
__device__ float g_acc[(size_t)N_NODES * D];   // zeroed by k_initcount each call
__device__ float g_deg[N_NODES];               // counted in k_initcount, zeroed by k_dot

// gx nnz sorted by DESTINATION edge (gxr): 500k bins
__device__ int  g_ecnt[N_EDGES];               // counted, then zeroed by k_scanA
__device__ int  g_ecur[N_EDGES];               // within-block-exclusive prefix (scanA), bumped by scatter
__device__ int  g_part[GX_BLOCKS];             // block sums -> exclusive (scanB)
__device__ int4 g_es4[NNZ_GX];                 // {tu[c]|ti[c]<<16, tu[r]|ti[r]<<16, vbits, cidx}

// g nnz sorted by DESTINATION row: 100k bins
__device__ int  g_gcnt[N_NODES];
__device__ int  g_gcur[N_NODES];
__device__ int  g_gpart[G_BLOCKS];
__device__ int4 g_gs4[NNZ_G];                  // {col, row, vbits, 0}

// fire-and-forget vector reduction (RED.E.ADD.F32x4), sm_90+
__device__ __forceinline__ void red_add_f32x4(float4* addr, float4 v) {
    asm volatile("red.global.add.v4.f32 [%0], {%1, %2, %3, %4};"
                 :: "l"(addr), "f"(v.x), "f"(v.y), "f"(v.z), "f"(v.w)
                 : "memory");
}

// 1: init A/acc + count gx-by-dst-edge, g-by-row, node degrees
__global__ void k_initcount(const float* __restrict__ ue, const float* __restrict__ ie,
                            const int* __restrict__ gxr, const int* __restrict__ grows,
                            const int* __restrict__ tu, const int* __restrict__ ti) {
    int t = blockIdx.x * blockDim.x + threadIdx.x;
    if (t < N_NODES * DV) {
        float4 v;
        if (t < NUM_USERS * DV) v = ((const float4*)ue)[t];
        else                    v = ((const float4*)ie)[t - NUM_USERS * DV];
        ((float4*)g_A)[t]   = v;
        ((float4*)g_acc)[t] = make_float4(0.f, 0.f, 0.f, 0.f);
    }
    if (t < NNZ_GX) atomicAdd(&g_ecnt[gxr[t]], 1);
    if (t < NNZ_G)  atomicAdd(&g_gcnt[grows[t]], 1);
    if (t < N_EDGES) {
        atomicAdd(&g_deg[tu[t]], 1.f);
        atomicAdd(&g_deg[NUM_USERS + ti[t]], 1.f);
    }
}

// 2: block-local scan: each block covers 2048 bins; writes within-block
//    exclusive prefixes to cur, block total to part, zeroes cnt behind itself.
__global__ void k_scanA() {
    __shared__ int sh[256];
    int b = blockIdx.x;
    int tid = threadIdx.x;
    int *cnt, *cur, *part;
    int n, base_bin, pidx;
    if (b < GX_BLOCKS) { cnt = g_ecnt; cur = g_ecur; part = g_part;  n = N_EDGES; base_bin = b * BINS_PER_BLOCK; pidx = b; }
    else               { cnt = g_gcnt; cur = g_gcur; part = g_gpart; n = N_NODES; base_bin = (b - GX_BLOCKS) * BINS_PER_BLOCK; pidx = b - GX_BLOCKS; }
    int i0 = base_bin + tid * 8;
    int c[8], pre[8];
    #pragma unroll
    for (int k = 0; k < 8; ++k) {
        int i = i0 + k;
        c[k] = (i < n) ? cnt[i] : 0;
    }
    pre[0] = 0;
    #pragma unroll
    for (int k = 1; k < 8; ++k) pre[k] = pre[k - 1] + c[k - 1];
    int s = pre[7] + c[7];
    sh[tid] = s;
    __syncthreads();
    for (int o = 1; o < 256; o <<= 1) {
        int v = (tid >= o) ? sh[tid - o] : 0;
        __syncthreads();
        sh[tid] += v;
        __syncthreads();
    }
    int base = (tid == 0) ? 0 : sh[tid - 1];
    #pragma unroll
    for (int k = 0; k < 8; ++k) {
        int i = i0 + k;
        if (i < n) { cur[i] = base + pre[k]; cnt[i] = 0; }
    }
    if (tid == 255) part[pidx] = sh[255];
}

// 3: single tiny block: exclusive-scan the two part arrays in place
__global__ void k_scanB() {
    __shared__ int sh[256];
    int tid = threadIdx.x;
    int v = (tid < GX_BLOCKS) ? g_part[tid] : 0;
    sh[tid] = v;
    __syncthreads();
    for (int o = 1; o < 256; o <<= 1) {
        int u = (tid >= o) ? sh[tid - o] : 0;
        __syncthreads();
        sh[tid] += u;
        __syncthreads();
    }
    if (tid < GX_BLOCKS) g_part[tid] = sh[tid] - v;   // exclusive
    __syncthreads();
    int w = (tid < G_BLOCKS) ? g_gpart[tid] : 0;
    sh[tid] = w;
    __syncthreads();
    for (int o = 1; o < 256; o <<= 1) {
        int u = (tid >= o) ? sh[tid - o] : 0;
        __syncthreads();
        sh[tid] += u;
        __syncthreads();
    }
    if (tid < G_BLOCKS) g_gpart[tid] = sh[tid] - w;
}

// 4: scatter both nnz streams into dst-sorted flat-entry arrays
//    (global position = block-local cur atomic + scanned block base)
__global__ void k_scatter(const int* __restrict__ gxr, const int* __restrict__ gxc,
                          const float* __restrict__ gxv,
                          const int* __restrict__ grows, const int* __restrict__ gcols,
                          const float* __restrict__ gvals,
                          const int* __restrict__ tu, const int* __restrict__ ti,
                          const int* __restrict__ i2c) {
    int t = blockIdx.x * blockDim.x + threadIdx.x;
    if (t < NNZ_GX) {
        int r = gxr[t];
        int c = gxc[t];
        unsigned suc = (unsigned)tu[c];
        unsigned sic = (unsigned)ti[c];
        unsigned dur = (unsigned)tu[r];
        unsigned dir = (unsigned)ti[r];
        int cidx = i2c[(int)sic];
        int p = atomicAdd(&g_ecur[r], 1) + g_part[r >> 11];
        g_es4[p] = make_int4((int)(suc | (sic << 16)),
                             (int)(dur | (dir << 16)),
                             __float_as_int(gxv[t]), cidx);
    }
    if (t < NNZ_G) {
        int row = grows[t];
        int p = atomicAdd(&g_gcur[row], 1) + g_gpart[row >> 11];
        g_gs4[p] = make_int4(gcols[t], row, __float_as_int(gvals[t]), 0);
    }
}

// 5: push spmm over row-sorted entries; merge REDs when pair shares the row
__global__ void __launch_bounds__(256) k_spmm_g() {
    int t = blockIdx.x * blockDim.x + threadIdx.x;   // < NNZ_G/2 * 16 = 8M
    int p = t >> 4;
    int j = t & 15;
    if (p >= NNZ_G / 2) return;
    int4 Ea = g_gs4[2 * p];
    int4 Eb = g_gs4[2 * p + 1];
    const float4* Av = (const float4*)g_A;
    float4 x0 = Av[Ea.x * DV + j];
    float4 x1 = Av[Eb.x * DV + j];
    float va = __int_as_float(Ea.z);
    float vb = __int_as_float(Eb.z);
    float4 y0 = make_float4(va * x0.x, va * x0.y, va * x0.z, va * x0.w);
    float4 y1 = make_float4(vb * x1.x, vb * x1.y, vb * x1.z, vb * x1.w);
    float4* Bv = (float4*)g_B;
    if (Ea.y == Eb.y) {
        y0.x += y1.x; y0.y += y1.y; y0.z += y1.z; y0.w += y1.w;
        red_add_f32x4(Bv + Ea.y * DV + j, y0);
    } else {
        red_add_f32x4(Bv + Ea.y * DV + j, y0);
        red_add_f32x4(Bv + Eb.y * DV + j, y1);
    }
}

// 6: gx push over dst-sorted entries; merge RED pairs when dst-pack matches
template <int LAYER0>
__global__ void __launch_bounds__(256) k_gx(const float* __restrict__ cat) {
    int t = blockIdx.x * blockDim.x + threadIdx.x;   // < NNZ_GX/2 * 16 = 16M
    int p = t >> 4;
    int j = t & 15;
    if (p >= NNZ_GX / 2) return;
    int4 Ea = g_es4[2 * p];
    int4 Eb = g_es4[2 * p + 1];
    const float4* Bv = (const float4*)g_B;
    unsigned sa = (unsigned)Ea.x, sb = (unsigned)Eb.x;
    float4 xa0 = Bv[(int)(sa & 0xFFFFu) * DV + j];
    float4 xa1 = Bv[(NUM_USERS + (int)(sa >> 16)) * DV + j];
    float4 xb0 = Bv[(int)(sb & 0xFFFFu) * DV + j];
    float4 xb1 = Bv[(NUM_USERS + (int)(sb >> 16)) * DV + j];
    if (LAYER0) {
        const float4* catv = (const float4*)cat;
        float4 ca0 = catv[Ea.w * 32 + j];
        float4 ca1 = catv[Ea.w * 32 + 16 + j];
        float4 cb0 = catv[Eb.w * 32 + j];
        float4 cb1 = catv[Eb.w * 32 + 16 + j];
        xa0.x += ca0.x; xa0.y += ca0.y; xa0.z += ca0.z; xa0.w += ca0.w;
        xa1.x += ca1.x; xa1.y += ca1.y; xa1.z += ca1.z; xa1.w += ca1.w;
        xb0.x += cb0.x; xb0.y += cb0.y; xb0.z += cb0.z; xb0.w += cb0.w;
        xb1.x += cb1.x; xb1.y += cb1.y; xb1.z += cb1.z; xb1.w += cb1.w;
    }
    float va = __int_as_float(Ea.z);
    float vb = __int_as_float(Eb.z);
    float4 ya0 = make_float4(va * xa0.x, va * xa0.y, va * xa0.z, va * xa0.w);
    float4 ya1 = make_float4(va * xa1.x, va * xa1.y, va * xa1.z, va * xa1.w);
    float4 yb0 = make_float4(vb * xb0.x, vb * xb0.y, vb * xb0.z, vb * xb0.w);
    float4 yb1 = make_float4(vb * xb1.x, vb * xb1.y, vb * xb1.z, vb * xb1.w);
    float4* Uv = (float4*)g_U;
    unsigned da = (unsigned)Ea.y, db = (unsigned)Eb.y;
    int dua = (int)(da & 0xFFFFu), dia = NUM_USERS + (int)(da >> 16);
    if (da == db) {
        ya0.x += yb0.x; ya0.y += yb0.y; ya0.z += yb0.z; ya0.w += yb0.w;
        ya1.x += yb1.x; ya1.y += yb1.y; ya1.z += yb1.z; ya1.w += yb1.w;
        red_add_f32x4(Uv + dua * DV + j, ya0);
        red_add_f32x4(Uv + dia * DV + j, ya1);
    } else {
        int dub = (int)(db & 0xFFFFu), dib = NUM_USERS + (int)(db >> 16);
        red_add_f32x4(Uv + dua * DV + j, ya0);
        red_add_f32x4(Uv + dia * DV + j, ya1);
        red_add_f32x4(Uv + dub * DV + j, yb0);
        red_add_f32x4(Uv + dib * DV + j, yb1);
    }
}

// A = 0.5 * (U/(deg+1e-9) + B);  acc += A;  zero B,U for next layer/replay
__global__ void k_combine() {
    int t0 = (blockIdx.x * blockDim.x + threadIdx.x) * 2;
    if (t0 >= N_NODES * DV) return;
    float4 z = make_float4(0.f, 0.f, 0.f, 0.f);
    #pragma unroll
    for (int q = 0; q < 2; ++q) {
        int t = t0 + q;
        int n = t >> 4;
        float inv = 0.5f / (g_deg[n] + 1e-9f);
        float4 u = ((const float4*)g_U)[t];
        float4 b = ((const float4*)g_B)[t];
        float4 a;
        a.x = u.x * inv + 0.5f * b.x;
        a.y = u.y * inv + 0.5f * b.y;
        a.z = u.z * inv + 0.5f * b.z;
        a.w = u.w * inv + 0.5f * b.w;
        ((float4*)g_A)[t] = a;
        float4 ac = ((float4*)g_acc)[t];
        ac.x += a.x; ac.y += a.y; ac.z += a.z; ac.w += a.w;
        ((float4*)g_acc)[t] = ac;
        ((float4*)g_B)[t] = z;
        ((float4*)g_U)[t] = z;
    }
}

// gamma[b] = dot(acc[u], acc[50000+i]) / 9; zero deg for next replay
__global__ void k_dot(const int* __restrict__ users, const int* __restrict__ items,
                      float* __restrict__ out) {
    int t = blockIdx.x * blockDim.x + threadIdx.x;
    if (t < N_NODES) g_deg[t] = 0.f;
    int b = t >> 5;
    if (b >= BATCH) return;
    int lane = t & 31;
    const float2* au = (const float2*)(g_acc + (size_t)users[b] * D);
    const float2* ai = (const float2*)(g_acc + (size_t)(NUM_USERS + items[b]) * D);
    float2 x = au[lane], y = ai[lane];
    float s = x.x * y.x + x.y * y.y;
    #pragma unroll
    for (int o = 16; o; o >>= 1) s += __shfl_down_sync(0xffffffffu, s, o);
    if (lane == 0) out[b] = s * (1.f / 9.f);
}

extern "C" void kernel_launch(void* const* d_in, const int* in_sizes, int n_in,
                              void* d_out, int out_size) {
    const float* user_emb = (const float*)d_in[0];
    const float* item_emb = (const float*)d_in[1];
    const float* cat_emb  = (const float*)d_in[2];
    const float* g_vals   = (const float*)d_in[3];
    const float* gx_vals  = (const float*)d_in[4];
    const int*   g_rows   = (const int*)d_in[5];
    const int*   g_cols   = (const int*)d_in[6];
    const int*   gx_rows  = (const int*)d_in[7];
    const int*   gx_cols  = (const int*)d_in[8];
    const int*   tu       = (const int*)d_in[9];
    const int*   ti       = (const int*)d_in[10];
    const int*   i2c      = (const int*)d_in[11];
    const int*   users    = (const int*)d_in[12];
    const int*   items    = (const int*)d_in[13];
    float* out = (float*)d_out;

    const int TB = 256;
    int big_grid  = (NNZ_GX + TB - 1) / TB;              // 7813
    int comb_grid = (N_NODES * DV / 2 + TB - 1) / TB;    // 3125
    int g_grid    = (NNZ_G / 2 * 16) / TB;               // 31250
    int gx_grid   = (NNZ_GX / 2 * 16) / TB;              // 62500
    int dot_grid  = (BATCH * 32 + TB - 1) / TB;          // 1024

    k_initcount<<<big_grid, TB>>>(user_emb, item_emb, gx_rows, g_rows, tu, ti); // 1
    k_scanA<<<GX_BLOCKS + G_BLOCKS, TB>>>();                                    // 2
    k_scanB<<<1, TB>>>();                                                       // 3
    k_scatter<<<big_grid, TB>>>(gx_rows, gx_cols, gx_vals,
                                g_rows, g_cols, g_vals, tu, ti, i2c);           // 4 <- profiled
    for (int L = 0; L < 3; ++L) {
        k_spmm_g<<<g_grid, TB>>>();
        if (L == 0) k_gx<1><<<gx_grid, TB>>>(cat_emb);
        else        k_gx<0><<<gx_grid, TB>>>(cat_emb);
        k_combine<<<comb_grid, TB>>>();
    }
    k_dot<<<dot_grid, TB>>>(users, items, out);
}

// round 13
// speedup vs baseline: 2.8338x; 1.1083x over previous
#include <cuda_runtime.h>

#define NUM_USERS 50000
#define NUM_ITEMS 50000
#define D 64
#define DV 16
#define N_NODES (NUM_USERS + NUM_ITEMS)
#define N_EDGES 500000
#define NNZ_G 1000000
#define NNZ_GX 2000000
#define BATCH 8192

#define BINS_PER_BLOCK 2048                 // 256 threads x 8 bins
#define GX_BLOCKS 245                       // ceil(500000/2048)
#define G_BLOCKS  49                        // ceil(100000/2048)

// ---- static device scratch (zero-init at load; replay-safe state machine) ----
__device__ float g_A[(size_t)N_NODES * D];
__device__ float g_B[(size_t)N_NODES * D];     // zeroed by k_combine each layer
__device__ float g_U[(size_t)N_NODES * D];     // ditto
__device__ float g_acc[(size_t)N_NODES * D];   // zeroed by k_initcount each call
__device__ float g_deg[N_NODES];               // counted in k_initcount, zeroed by k_dot
__device__ int2  g_pe[N_EDGES];                // {tu[e]|ti[e]<<16, i2c[ti[e]]}

// gx nnz sorted by DESTINATION edge (gxr): 500k bins
__device__ int  g_ecnt[N_EDGES];               // counted, then zeroed by k_scanA
__device__ int  g_ecur[N_EDGES];
__device__ int  g_part[GX_BLOCKS];
__device__ int4 g_es4[NNZ_GX];                 // {srcpack, dstpack, vbits, cidx}

// g nnz sorted by DESTINATION row: 100k bins
__device__ int  g_gcnt[N_NODES];
__device__ int  g_gcur[N_NODES];
__device__ int  g_gpart[G_BLOCKS];
__device__ int4 g_gs4[NNZ_G];                  // {col, row, vbits, 0}

// fire-and-forget vector reduction (RED.E.ADD.F32x4), sm_90+
__device__ __forceinline__ void red_add_f32x4(float4* addr, float4 v) {
    asm volatile("red.global.add.v4.f32 [%0], {%1, %2, %3, %4};"
                 :: "l"(addr), "f"(v.x), "f"(v.y), "f"(v.z), "f"(v.w)
                 : "memory");
}
__device__ __forceinline__ void f4add(float4& a, const float4& b) {
    a.x += b.x; a.y += b.y; a.z += b.z; a.w += b.w;
}

// 1: init A/acc + counts + degree + edge-pack table
__global__ void k_initcount(const float* __restrict__ ue, const float* __restrict__ ie,
                            const int* __restrict__ gxr, const int* __restrict__ grows,
                            const int* __restrict__ tu, const int* __restrict__ ti,
                            const int* __restrict__ i2c) {
    int t = blockIdx.x * blockDim.x + threadIdx.x;
    if (t < N_NODES * DV) {
        float4 v;
        if (t < NUM_USERS * DV) v = ((const float4*)ue)[t];
        else                    v = ((const float4*)ie)[t - NUM_USERS * DV];
        ((float4*)g_A)[t]   = v;
        ((float4*)g_acc)[t] = make_float4(0.f, 0.f, 0.f, 0.f);
    }
    if (t < NNZ_GX) atomicAdd(&g_ecnt[gxr[t]], 1);
    if (t < NNZ_G)  atomicAdd(&g_gcnt[grows[t]], 1);
    if (t < N_EDGES) {
        int u = tu[t], it = ti[t];
        atomicAdd(&g_deg[u], 1.f);
        atomicAdd(&g_deg[NUM_USERS + it], 1.f);
        g_pe[t] = make_int2((int)((unsigned)u | ((unsigned)it << 16)), i2c[it]);
    }
}

// 2: block-local scans; zero counts behind
__global__ void k_scanA() {
    __shared__ int sh[256];
    int b = blockIdx.x;
    int tid = threadIdx.x;
    int *cnt, *cur, *part;
    int n, base_bin, pidx;
    if (b < GX_BLOCKS) { cnt = g_ecnt; cur = g_ecur; part = g_part;  n = N_EDGES; base_bin = b * BINS_PER_BLOCK; pidx = b; }
    else               { cnt = g_gcnt; cur = g_gcur; part = g_gpart; n = N_NODES; base_bin = (b - GX_BLOCKS) * BINS_PER_BLOCK; pidx = b - GX_BLOCKS; }
    int i0 = base_bin + tid * 8;
    int c[8], pre[8];
    #pragma unroll
    for (int k = 0; k < 8; ++k) {
        int i = i0 + k;
        c[k] = (i < n) ? cnt[i] : 0;
    }
    pre[0] = 0;
    #pragma unroll
    for (int k = 1; k < 8; ++k) pre[k] = pre[k - 1] + c[k - 1];
    int s = pre[7] + c[7];
    sh[tid] = s;
    __syncthreads();
    for (int o = 1; o < 256; o <<= 1) {
        int v = (tid >= o) ? sh[tid - o] : 0;
        __syncthreads();
        sh[tid] += v;
        __syncthreads();
    }
    int base = (tid == 0) ? 0 : sh[tid - 1];
    #pragma unroll
    for (int k = 0; k < 8; ++k) {
        int i = i0 + k;
        if (i < n) { cur[i] = base + pre[k]; cnt[i] = 0; }
    }
    if (tid == 255) part[pidx] = sh[255];
}

// 3: scan the block-sum arrays
__global__ void k_scanB() {
    __shared__ int sh[256];
    int tid = threadIdx.x;
    int v = (tid < GX_BLOCKS) ? g_part[tid] : 0;
    sh[tid] = v;
    __syncthreads();
    for (int o = 1; o < 256; o <<= 1) {
        int u = (tid >= o) ? sh[tid - o] : 0;
        __syncthreads();
        sh[tid] += u;
        __syncthreads();
    }
    if (tid < GX_BLOCKS) g_part[tid] = sh[tid] - v;
    __syncthreads();
    int w = (tid < G_BLOCKS) ? g_gpart[tid] : 0;
    sh[tid] = w;
    __syncthreads();
    for (int o = 1; o < 256; o <<= 1) {
        int u = (tid >= o) ? sh[tid - o] : 0;
        __syncthreads();
        sh[tid] += u;
        __syncthreads();
    }
    if (tid < G_BLOCKS) g_gpart[tid] = sh[tid] - w;
}

// 4: scatter via edge-pack table (2 random 8B loads/nnz instead of 5x4B)
__global__ void k_scatter(const int* __restrict__ gxr, const int* __restrict__ gxc,
                          const float* __restrict__ gxv,
                          const int* __restrict__ grows, const int* __restrict__ gcols,
                          const float* __restrict__ gvals) {
    int t = blockIdx.x * blockDim.x + threadIdx.x;
    if (t < NNZ_GX) {
        int r = gxr[t];
        int c = gxc[t];
        int2 pc = g_pe[c];
        int2 pr = g_pe[r];
        int p = atomicAdd(&g_ecur[r], 1) + g_part[r >> 11];
        g_es4[p] = make_int4(pc.x, pr.x, __float_as_int(gxv[t]), pc.y);
    }
    if (t < NNZ_G) {
        int row = grows[t];
        int p = atomicAdd(&g_gcur[row], 1) + g_gpart[row >> 11];
        g_gs4[p] = make_int4(gcols[t], row, __float_as_int(gvals[t]), 0);
    }
}

// 5: push spmm, 4 nnz/thread, run-merge REDs by row
__global__ void __launch_bounds__(256) k_spmm_g() {
    int t = blockIdx.x * blockDim.x + threadIdx.x;   // < NNZ_G/4 * 16 = 4M
    int p = t >> 4;
    int j = t & 15;
    if (p >= NNZ_G / 4) return;
    int4 E[4];
    #pragma unroll
    for (int k = 0; k < 4; ++k) E[k] = g_gs4[4 * p + k];
    const float4* Av = (const float4*)g_A;
    float4 y[4];
    #pragma unroll
    for (int k = 0; k < 4; ++k) {
        float4 x = Av[E[k].x * DV + j];
        float v = __int_as_float(E[k].z);
        y[k] = make_float4(v * x.x, v * x.y, v * x.z, v * x.w);
    }
    float4* Bv = (float4*)g_B;
    float4 acc = y[0];
    int cur = E[0].y;
    #pragma unroll
    for (int k = 1; k < 4; ++k) {
        if (E[k].y == cur) { f4add(acc, y[k]); }
        else {
            red_add_f32x4(Bv + cur * DV + j, acc);
            cur = E[k].y;
            acc = y[k];
        }
    }
    red_add_f32x4(Bv + cur * DV + j, acc);
}

// 6: gx push, 4 nnz/thread, run-merge RED pairs by dst-pack
template <int LAYER0>
__global__ void __launch_bounds__(256) k_gx(const float* __restrict__ cat) {
    int t = blockIdx.x * blockDim.x + threadIdx.x;   // < NNZ_GX/4 * 16 = 8M
    int p = t >> 4;
    int j = t & 15;
    if (p >= NNZ_GX / 4) return;
    int4 E[4];
    #pragma unroll
    for (int k = 0; k < 4; ++k) E[k] = g_es4[4 * p + k];
    const float4* Bv = (const float4*)g_B;
    const float4* catv = (const float4*)cat;
    float4 yu[4], yi[4];
    #pragma unroll
    for (int k = 0; k < 4; ++k) {
        unsigned s = (unsigned)E[k].x;
        float4 x0 = Bv[(int)(s & 0xFFFFu) * DV + j];
        float4 x1 = Bv[(NUM_USERS + (int)(s >> 16)) * DV + j];
        if (LAYER0) {
            float4 c0 = catv[E[k].w * 32 + j];
            float4 c1 = catv[E[k].w * 32 + 16 + j];
            f4add(x0, c0);
            f4add(x1, c1);
        }
        float v = __int_as_float(E[k].z);
        yu[k] = make_float4(v * x0.x, v * x0.y, v * x0.z, v * x0.w);
        yi[k] = make_float4(v * x1.x, v * x1.y, v * x1.z, v * x1.w);
    }
    float4* Uv = (float4*)g_U;
    float4 au = yu[0], ai = yi[0];
    unsigned cur = (unsigned)E[0].y;
    #pragma unroll
    for (int k = 1; k < 4; ++k) {
        unsigned d = (unsigned)E[k].y;
        if (d == cur) { f4add(au, yu[k]); f4add(ai, yi[k]); }
        else {
            red_add_f32x4(Uv + (int)(cur & 0xFFFFu) * DV + j, au);
            red_add_f32x4(Uv + (NUM_USERS + (int)(cur >> 16)) * DV + j, ai);
            cur = d;
            au = yu[k];
            ai = yi[k];
        }
    }
    red_add_f32x4(Uv + (int)(cur & 0xFFFFu) * DV + j, au);
    red_add_f32x4(Uv + (NUM_USERS + (int)(cur >> 16)) * DV + j, ai);
}

// A = 0.5 * (U/(deg+1e-9) + B);  acc += A;  zero B,U for next layer/replay
__global__ void k_combine() {
    int t0 = (blockIdx.x * blockDim.x + threadIdx.x) * 2;
    if (t0 >= N_NODES * DV) return;
    float4 z = make_float4(0.f, 0.f, 0.f, 0.f);
    #pragma unroll
    for (int q = 0; q < 2; ++q) {
        int t = t0 + q;
        int n = t >> 4;
        float inv = 0.5f / (g_deg[n] + 1e-9f);
        float4 u = ((const float4*)g_U)[t];
        float4 b = ((const float4*)g_B)[t];
        float4 a;
        a.x = u.x * inv + 0.5f * b.x;
        a.y = u.y * inv + 0.5f * b.y;
        a.z = u.z * inv + 0.5f * b.z;
        a.w = u.w * inv + 0.5f * b.w;
        ((float4*)g_A)[t] = a;
        float4 ac = ((float4*)g_acc)[t];
        f4add(ac, a);
        ((float4*)g_acc)[t] = ac;
        ((float4*)g_B)[t] = z;
        ((float4*)g_U)[t] = z;
    }
}

// gamma[b] = dot(acc[u], acc[50000+i]) / 9; zero deg for next replay
__global__ void k_dot(const int* __restrict__ users, const int* __restrict__ items,
                      float* __restrict__ out) {
    int t = blockIdx.x * blockDim.x + threadIdx.x;
    if (t < N_NODES) g_deg[t] = 0.f;
    int b = t >> 5;
    if (b >= BATCH) return;
    int lane = t & 31;
    const float2* au = (const float2*)(g_acc + (size_t)users[b] * D);
    const float2* ai = (const float2*)(g_acc + (size_t)(NUM_USERS + items[b]) * D);
    float2 x = au[lane], y = ai[lane];
    float s = x.x * y.x + x.y * y.y;
    #pragma unroll
    for (int o = 16; o; o >>= 1) s += __shfl_down_sync(0xffffffffu, s, o);
    if (lane == 0) out[b] = s * (1.f / 9.f);
}

extern "C" void kernel_launch(void* const* d_in, const int* in_sizes, int n_in,
                              void* d_out, int out_size) {
    const float* user_emb = (const float*)d_in[0];
    const float* item_emb = (const float*)d_in[1];
    const float* cat_emb  = (const float*)d_in[2];
    const float* g_vals   = (const float*)d_in[3];
    const float* gx_vals  = (const float*)d_in[4];
    const int*   g_rows   = (const int*)d_in[5];
    const int*   g_cols   = (const int*)d_in[6];
    const int*   gx_rows  = (const int*)d_in[7];
    const int*   gx_cols  = (const int*)d_in[8];
    const int*   tu       = (const int*)d_in[9];
    const int*   ti       = (const int*)d_in[10];
    const int*   i2c      = (const int*)d_in[11];
    const int*   users    = (const int*)d_in[12];
    const int*   items    = (const int*)d_in[13];
    float* out = (float*)d_out;

    const int TB = 256;
    int big_grid  = (NNZ_GX + TB - 1) / TB;              // 7813
    int comb_grid = (N_NODES * DV / 2 + TB - 1) / TB;    // 3125
    int g_grid    = (NNZ_G / 4 * 16) / TB;               // 15625
    int gx_grid   = (NNZ_GX / 4 * 16) / TB;              // 31250
    int dot_grid  = (BATCH * 32 + TB - 1) / TB;          // 1024

    k_initcount<<<big_grid, TB>>>(user_emb, item_emb, gx_rows, g_rows, tu, ti, i2c); // 1
    k_scanA<<<GX_BLOCKS + G_BLOCKS, TB>>>();                                         // 2
    k_scanB<<<1, TB>>>();                                                            // 3
    k_scatter<<<big_grid, TB>>>(gx_rows, gx_cols, gx_vals, g_rows, g_cols, g_vals);  // 4 <- profiled
    for (int L = 0; L < 3; ++L) {
        k_spmm_g<<<g_grid, TB>>>();
        if (L == 0) k_gx<1><<<gx_grid, TB>>>(cat_emb);
        else        k_gx<0><<<gx_grid, TB>>>(cat_emb);
        k_combine<<<comb_grid, TB>>>();
    }
    k_dot<<<dot_grid, TB>>>(users, items, out);
}